// round 2
// baseline (speedup 1.0000x reference)
#include <cuda_runtime.h>
#include <cstdint>

__device__ double g_partials[1024];

// One warp per row: fused gather-dot + squared norms, warp-shuffle reduce,
// per-block double partial sum. Labels dtype (int32 vs int64) detected on
// device: for int64 values in [0, C), all odd int32 words are zero.
__global__ void center_loss_rows(const float* __restrict__ x,
                                 const float* __restrict__ centers,
                                 const int* __restrict__ labels_raw,
                                 int B, int D, int C) {
    __shared__ int s_is64;
    if (threadIdx.x == 0) {
        int nsample = B < 128 ? B : 128;
        int any_odd_nonzero = 0;
        for (int i = 0; i < nsample; i++)
            any_odd_nonzero |= labels_raw[2 * i + 1];
        s_is64 = (any_odd_nonzero == 0);
    }
    __syncthreads();
    const int is64 = s_is64;

    const int lane = threadIdx.x & 31;
    const int warp_in_blk = threadIdx.x >> 5;
    const int warps_per_blk = blockDim.x >> 5;
    const int gwarp = blockIdx.x * warps_per_blk + warp_in_blk;
    const int nwarps = gridDim.x * warps_per_blk;
    const int n4 = D >> 2;

    double local = 0.0;

    for (int row = gwarp; row < B; row += nwarps) {
        long long li = is64 ? ((const long long*)labels_raw)[row]
                            : (long long)labels_raw[row];
        // defensive clamp — never allow OOB gather
        if (li < 0) li = 0;
        if (li >= C) li = C - 1;

        const float4* __restrict__ xr =
            reinterpret_cast<const float4*>(x + (size_t)row * D);
        const float4* __restrict__ cr =
            reinterpret_cast<const float4*>(centers + (size_t)li * D);

        float dot = 0.f, xsq = 0.f, csq = 0.f;
        #pragma unroll 4
        for (int i = lane; i < n4; i += 32) {
            float4 a = xr[i];
            float4 b = cr[i];
            dot = fmaf(a.x, b.x, fmaf(a.y, b.y, fmaf(a.z, b.z, fmaf(a.w, b.w, dot))));
            xsq = fmaf(a.x, a.x, fmaf(a.y, a.y, fmaf(a.z, a.z, fmaf(a.w, a.w, xsq))));
            csq = fmaf(b.x, b.x, fmaf(b.y, b.y, fmaf(b.z, b.z, fmaf(b.w, b.w, csq))));
        }
        #pragma unroll
        for (int o = 16; o > 0; o >>= 1) {
            dot += __shfl_down_sync(0xFFFFFFFFu, dot, o);
            xsq += __shfl_down_sync(0xFFFFFFFFu, xsq, o);
            csq += __shfl_down_sync(0xFFFFFFFFu, csq, o);
        }
        if (lane == 0) {
            float v = 0.5f * (xsq + csq) + 0.3f * dot;
            v = fminf(fmaxf(v, 1e-12f), 1e12f);
            local += (double)v;
        }
    }

    __shared__ double sdata[32];
    if (lane == 0) sdata[warp_in_blk] = local;
    __syncthreads();
    if (threadIdx.x == 0) {
        double s = 0.0;
        for (int i = 0; i < warps_per_blk; i++) s += sdata[i];
        g_partials[blockIdx.x] = s;
    }
}

__global__ void center_loss_finalize(float* __restrict__ out,
                                     int nblocks, long long B, long long C) {
    __shared__ double sdata[256];
    double s = 0.0;
    for (int i = threadIdx.x; i < nblocks; i += blockDim.x) s += g_partials[i];
    sdata[threadIdx.x] = s;
    __syncthreads();
    for (int o = 128; o > 0; o >>= 1) {
        if (threadIdx.x < o) sdata[threadIdx.x] += sdata[threadIdx.x + o];
        __syncthreads();
    }
    if (threadIdx.x == 0) {
        // every masked-out entry contributes clip(0, 1e-12, 1e12) = 1e-12
        double masked_zeros = ((double)B * (double)C - (double)B) * 1e-12;
        out[0] = (float)((sdata[0] + masked_zeros) / (double)B);
    }
}

extern "C" void kernel_launch(void* const* d_in, const int* in_sizes, int n_in,
                              void* d_out, int out_size) {
    const float* x = (const float*)d_in[0];
    const float* centers = (const float*)d_in[1];
    const int* labels = (const int*)d_in[2];
    float* out = (float*)d_out;

    const int B = in_sizes[2];                 // labels: [B]
    const int D = in_sizes[0] / B;             // x: [B, D]
    const int C = in_sizes[1] / D;             // centers: [C, D]

    const int threads = 256;                   // 8 warps/block
    const int warps_per_blk = threads / 32;
    int blocks = (B + warps_per_blk - 1) / warps_per_blk;
    if (blocks > 1024) blocks = 1024;

    center_loss_rows<<<blocks, threads>>>(x, centers, labels, B, D, C);
    center_loss_finalize<<<1, 256>>>(out, blocks, (long long)B, (long long)C);
}

// round 3
// speedup vs baseline: 1.1866x; 1.1866x over previous
#include <cuda_runtime.h>
#include <cstdint>

__device__ double g_partials[4096];
__device__ unsigned int g_done_count = 0;

// Fused: per-warp gathered dot/norm, per-block double partial, last-block
// final reduction (threadfence pattern, deterministic order).
__global__ void center_loss_fused(const float* __restrict__ x,
                                  const float* __restrict__ centers,
                                  const int* __restrict__ labels_raw,
                                  float* __restrict__ out,
                                  int B, int D, int C) {
    const int lane = threadIdx.x & 31;
    const int warp_in_blk = threadIdx.x >> 5;
    const int warps_per_blk = blockDim.x >> 5;
    const int gwarp = blockIdx.x * warps_per_blk + warp_in_blk;
    const int nwarps = gridDim.x * warps_per_blk;
    const int n4 = D >> 2;

    // ---- labels dtype detection (int64 iff all odd int32 words are 0) ----
    // warp 0 lanes sample 32 odd words in parallel; int64 labels in [0,C)
    // have zero high halves. P(false positive for int32) ~ (1/2^32)-ish.
    __shared__ int s_is64;
    if (threadIdx.x < 32) {
        int nsample = B < 32 ? B : 32;
        int v = (lane < nsample) ? labels_raw[2 * lane + 1] : 0;
        unsigned any = __ballot_sync(0xFFFFFFFFu, v != 0);
        if (lane == 0) s_is64 = (any == 0);
    }
    __syncthreads();
    const int is64 = s_is64;

    double local = 0.0;

    for (int row = gwarp; row < B; row += nwarps) {
        long long li = is64 ? ((const long long*)labels_raw)[row]
                            : (long long)labels_raw[row];
        if (li < 0) li = 0;
        if (li >= C) li = C - 1;

        const float4* __restrict__ xr =
            reinterpret_cast<const float4*>(x + (size_t)row * D);
        const float4* __restrict__ cr =
            reinterpret_cast<const float4*>(centers + (size_t)li * D);

        float dot = 0.f, xsq = 0.f, csq = 0.f;
        if (n4 == 128) {
            // D=512 fast path: fully unrolled -> max MLP (front-batched LDG.128)
            #pragma unroll
            for (int k = 0; k < 4; k++) {
                float4 a0 = xr[lane + k * 128 / 4 * 0 + k * 32];      // lane + k*32
                float4 b0 = cr[lane + k * 32];
                dot = fmaf(a0.x, b0.x, fmaf(a0.y, b0.y, fmaf(a0.z, b0.z, fmaf(a0.w, b0.w, dot))));
                xsq = fmaf(a0.x, a0.x, fmaf(a0.y, a0.y, fmaf(a0.z, a0.z, fmaf(a0.w, a0.w, xsq))));
                csq = fmaf(b0.x, b0.x, fmaf(b0.y, b0.y, fmaf(b0.z, b0.z, fmaf(b0.w, b0.w, csq))));
            }
        } else {
            #pragma unroll 4
            for (int i = lane; i < n4; i += 32) {
                float4 a = xr[i];
                float4 b = cr[i];
                dot = fmaf(a.x, b.x, fmaf(a.y, b.y, fmaf(a.z, b.z, fmaf(a.w, b.w, dot))));
                xsq = fmaf(a.x, a.x, fmaf(a.y, a.y, fmaf(a.z, a.z, fmaf(a.w, a.w, xsq))));
                csq = fmaf(b.x, b.x, fmaf(b.y, b.y, fmaf(b.z, b.z, fmaf(b.w, b.w, csq))));
            }
        }
        #pragma unroll
        for (int o = 16; o > 0; o >>= 1) {
            dot += __shfl_down_sync(0xFFFFFFFFu, dot, o);
            xsq += __shfl_down_sync(0xFFFFFFFFu, xsq, o);
            csq += __shfl_down_sync(0xFFFFFFFFu, csq, o);
        }
        if (lane == 0) {
            float v = 0.5f * (xsq + csq) + 0.3f * dot;
            v = fminf(fmaxf(v, 1e-12f), 1e12f);
            local += (double)v;
        }
    }

    // ---- block partial (double, deterministic) ----
    __shared__ double sdata[32];
    if (lane == 0) sdata[warp_in_blk] = local;
    __syncthreads();
    if (threadIdx.x == 0) {
        double s = 0.0;
        for (int i = 0; i < warps_per_blk; i++) s += sdata[i];
        g_partials[blockIdx.x] = s;
    }

    // ---- last-block-done final reduction (threadfence pattern) ----
    __shared__ bool s_last;
    __threadfence();
    if (threadIdx.x == 0) {
        unsigned int prev = atomicAdd(&g_done_count, 1u);
        s_last = (prev == gridDim.x - 1);
    }
    __syncthreads();
    if (s_last) {
        __shared__ double fin[256];
        double s = 0.0;
        for (int i = threadIdx.x; i < gridDim.x; i += blockDim.x)
            s += g_partials[i];
        fin[threadIdx.x] = s;
        __syncthreads();
        for (int o = blockDim.x >> 1; o > 0; o >>= 1) {
            if (threadIdx.x < (unsigned)o) fin[threadIdx.x] += fin[threadIdx.x + o];
            __syncthreads();
        }
        if (threadIdx.x == 0) {
            double masked_zeros = ((double)B * (double)C - (double)B) * 1e-12;
            out[0] = (float)((fin[0] + masked_zeros) / (double)B);
            g_done_count = 0;  // reset for next graph replay
        }
    }
}

extern "C" void kernel_launch(void* const* d_in, const int* in_sizes, int n_in,
                              void* d_out, int out_size) {
    const float* x = (const float*)d_in[0];
    const float* centers = (const float*)d_in[1];
    const int* labels = (const int*)d_in[2];
    float* out = (float*)d_out;

    const int B = in_sizes[2];
    const int D = in_sizes[0] / B;
    const int C = in_sizes[1] / D;

    const int threads = 256;  // 8 warps/block
    const int warps_per_blk = threads / 32;
    int blocks = (B + warps_per_blk - 1) / warps_per_blk;
    if (blocks > 4096) blocks = 4096;

    center_loss_fused<<<blocks, threads>>>(x, centers, labels, out, B, D, C);
}